// round 8
// baseline (speedup 1.0000x reference)
#include <cuda_runtime.h>
#include <cstdint>

#define B_DIM 4096
#define K_DIM 64
#define D_DIM 512
#define POOL_N 1000000
#define THREADS 512
#define SPLIT 2
#define K_PER (K_DIM / SPLIT)          // 32 rows per CTA
#define NWARP (THREADS / 32)           // 16 warps
#define ROWS_PER_WARP (K_PER / NWARP)  // 2 rows per warp

// smem: partials[NWARP][D] | x[D] | ret[D]
#define SMEM_FLOATS (NWARP * D_DIM + D_DIM + D_DIM)
#define SMEM_BYTES (SMEM_FLOATS * sizeof(float))

__global__ void __launch_bounds__(THREADS, 2) __cluster_dims__(2, 1, 1)
sparse_exec_kernel(const float* __restrict__ x,
                   const int* __restrict__ indices,
                   const float* __restrict__ weights,
                   const float* __restrict__ pool,
                   float* __restrict__ out) {
    extern __shared__ float smem[];
    float* s_part = smem;                        // NWARP * D
    float* s_x    = smem + NWARP * D_DIM;        // D
    float* s_ret  = s_x + D_DIM;                 // D (rank0 receives rank1's partial here)

    const int b    = blockIdx.x >> 1;
    const int tid  = threadIdx.x;
    const int warp = tid >> 5;
    const int lane = tid & 31;

    unsigned int rank;
    asm("mov.u32 %0, %%cluster_ctarank;" : "=r"(rank));
    const int kbase = rank * K_PER;

    // x[b] into shared (coalesced 2KB)
    s_x[tid] = x[(size_t)b * D_DIM + tid];
    __syncthreads();

    // ---- per-warp: gather 2 rows, dot, tanh*w, weighted partial ----
    int idxs[ROWS_PER_WARP];
#pragma unroll
    for (int r = 0; r < ROWS_PER_WARP; r++) {
        int k = warp * ROWS_PER_WARP + r;
        int v = indices[(size_t)b * K_DIM + kbase + k];
        v = v < 0 ? 0 : (v >= POOL_N ? POOL_N - 1 : v);
        idxs[r] = v;
    }

    // Issue all 8 global loads up-front (MLP=8 per thread)
    float4 v[ROWS_PER_WARP][4];
#pragma unroll
    for (int r = 0; r < ROWS_PER_WARP; r++) {
        const float4* prow = (const float4*)(pool + (size_t)idxs[r] * D_DIM);
#pragma unroll
        for (int i = 0; i < 4; i++)
            v[r][i] = __ldg(&prow[i * 32 + lane]);
    }

    const float4* sx4 = (const float4*)s_x;
    float4 xr[4];
#pragma unroll
    for (int i = 0; i < 4; i++)
        xr[i] = sx4[i * 32 + lane];

    float dot[ROWS_PER_WARP];
#pragma unroll
    for (int r = 0; r < ROWS_PER_WARP; r++) {
        float d = 0.0f;
#pragma unroll
        for (int i = 0; i < 4; i++)
            d += v[r][i].x * xr[i].x + v[r][i].y * xr[i].y
               + v[r][i].z * xr[i].z + v[r][i].w * xr[i].w;
#pragma unroll
        for (int off = 16; off; off >>= 1)
            d += __shfl_xor_sync(0xffffffffu, d, off);
        dot[r] = d;
    }

    float wa[ROWS_PER_WARP];
#pragma unroll
    for (int r = 0; r < ROWS_PER_WARP; r++) {
        int k = warp * ROWS_PER_WARP + r;
        wa[r] = tanhf(dot[r]) * __ldg(&weights[(size_t)b * K_DIM + kbase + k]);
    }

    float4* pw = (float4*)(s_part + warp * D_DIM);
#pragma unroll
    for (int i = 0; i < 4; i++) {
        float4 p;
        p.x = wa[0] * v[0][i].x + wa[1] * v[1][i].x;
        p.y = wa[0] * v[0][i].y + wa[1] * v[1][i].y;
        p.z = wa[0] * v[0][i].z + wa[1] * v[1][i].z;
        p.w = wa[0] * v[0][i].w + wa[1] * v[1][i].w;
        pw[i * 32 + lane] = p;
    }
    __syncthreads();

    // ---- reduce 16 warp partials (conflict-free: consecutive tid) ----
    float acc = 0.0f;
#pragma unroll
    for (int w = 0; w < NWARP; w++)
        acc += s_part[w * D_DIM + tid];

    // ---- cluster reduction: rank1 pushes its partial into rank0's s_ret ----
    if (rank == 1) {
        unsigned int laddr = (unsigned int)__cvta_generic_to_shared(&s_ret[tid]);
        unsigned int raddr;
        asm volatile("mapa.shared::cluster.u32 %0, %1, %2;"
                     : "=r"(raddr) : "r"(laddr), "r"(0u));
        asm volatile("st.shared::cluster.f32 [%0], %1;"
                     :: "r"(raddr), "f"(acc) : "memory");
    }
    // release/acquire cluster barrier orders the remote store before the read
    asm volatile("barrier.cluster.arrive.aligned;" ::: "memory");
    asm volatile("barrier.cluster.wait.aligned;" ::: "memory");

    if (rank == 0)
        out[(size_t)b * D_DIM + tid] = s_x[tid] + acc + s_ret[tid];
}

extern "C" void kernel_launch(void* const* d_in, const int* in_sizes, int n_in,
                              void* d_out, int out_size) {
    const float* x       = (const float*)d_in[0];
    const int*   indices = (const int*)d_in[1];
    const float* weights = (const float*)d_in[2];
    const float* pool    = (const float*)d_in[3];
    float*       out     = (float*)d_out;

    cudaFuncSetAttribute(sparse_exec_kernel,
                         cudaFuncAttributeMaxDynamicSharedMemorySize, SMEM_BYTES);

    sparse_exec_kernel<<<B_DIM * SPLIT, THREADS, SMEM_BYTES>>>(
        x, indices, weights, pool, out);
}

// round 11
// speedup vs baseline: 1.0218x; 1.0218x over previous
#include <cuda_runtime.h>
#include <cstdint>

#define B_DIM 4096
#define K_DIM 64
#define D_DIM 512
#define POOL_N 1000000
#define THREADS 512
#define SPLIT 2
#define K_PER (K_DIM / SPLIT)          // 32 rows per CTA
#define NWARP (THREADS / 32)           // 16 warps
#define ROWS_PER_WARP (K_PER / NWARP)  // 2 rows per warp

// smem: partials[NWARP][D] | x[D]
#define SMEM_FLOATS (NWARP * D_DIM + D_DIM)
#define SMEM_BYTES (SMEM_FLOATS * sizeof(float))

__device__ float g_scratch[(size_t)B_DIM * D_DIM];

__global__ void __launch_bounds__(THREADS, 2)
sparse_gather_kernel(const float* __restrict__ x,
                     const int* __restrict__ indices,
                     const float* __restrict__ weights,
                     const float* __restrict__ pool,
                     float* __restrict__ out) {
    extern __shared__ float smem[];
    float* s_part = smem;                      // NWARP * D
    float* s_x    = smem + NWARP * D_DIM;      // D

    const int b     = blockIdx.x >> 1;
    const int split = blockIdx.x & 1;
    const int tid   = threadIdx.x;
    const int warp  = tid >> 5;
    const int lane  = tid & 31;
    const int kbase = split * K_PER;

    // ---- 1. Issue index + weight loads FIRST (critical chain: idx -> pool) ----
    int idxs[ROWS_PER_WARP];
    float w[ROWS_PER_WARP];
#pragma unroll
    for (int r = 0; r < ROWS_PER_WARP; r++) {
        int k = warp * ROWS_PER_WARP + r;
        idxs[r] = indices[(size_t)b * K_DIM + kbase + k];
        w[r]    = __ldg(&weights[(size_t)b * K_DIM + kbase + k]);
    }

    // ---- 2. x load (overlaps index latency) ----
    float xv = x[(size_t)b * D_DIM + tid];

    // ---- 3. As soon as indices land: clamp + fire all 8 pool LDG.128 ----
#pragma unroll
    for (int r = 0; r < ROWS_PER_WARP; r++) {
        int t = idxs[r];
        idxs[r] = t < 0 ? 0 : (t >= POOL_N ? POOL_N - 1 : t);
    }
    float4 v[ROWS_PER_WARP][4];
#pragma unroll
    for (int r = 0; r < ROWS_PER_WARP; r++) {
        const float4* prow = (const float4*)(pool + (size_t)idxs[r] * D_DIM);
#pragma unroll
        for (int i = 0; i < 4; i++)
            v[r][i] = __ldg(&prow[i * 32 + lane]);
    }

    // ---- 4. x -> smem + barrier, overlapped behind pool-load latency ----
    s_x[tid] = xv;
    __syncthreads();

    const float4* sx4 = (const float4*)s_x;
    float4 xr[4];
#pragma unroll
    for (int i = 0; i < 4; i++)
        xr[i] = sx4[i * 32 + lane];

    // ---- 5. dots + warp reduce ----
    float dot[ROWS_PER_WARP];
#pragma unroll
    for (int r = 0; r < ROWS_PER_WARP; r++) {
        float d = 0.0f;
#pragma unroll
        for (int i = 0; i < 4; i++)
            d += v[r][i].x * xr[i].x + v[r][i].y * xr[i].y
               + v[r][i].z * xr[i].z + v[r][i].w * xr[i].w;
#pragma unroll
        for (int off = 16; off; off >>= 1)
            d += __shfl_xor_sync(0xffffffffu, d, off);
        dot[r] = d;
    }

    float wa[ROWS_PER_WARP];
#pragma unroll
    for (int r = 0; r < ROWS_PER_WARP; r++)
        wa[r] = tanhf(dot[r]) * w[r];

    // ---- 6. per-warp weighted partial straight from registers ----
    float4* pw = (float4*)(s_part + warp * D_DIM);
#pragma unroll
    for (int i = 0; i < 4; i++) {
        float4 p;
        p.x = wa[0] * v[0][i].x + wa[1] * v[1][i].x;
        p.y = wa[0] * v[0][i].y + wa[1] * v[1][i].y;
        p.z = wa[0] * v[0][i].z + wa[1] * v[1][i].z;
        p.w = wa[0] * v[0][i].w + wa[1] * v[1][i].w;
        pw[i * 32 + lane] = p;
    }
    __syncthreads();

    // ---- 7. reduce 16 warp partials (conflict-free) ----
    float acc = 0.0f;
#pragma unroll
    for (int wq = 0; wq < NWARP; wq++)
        acc += s_part[wq * D_DIM + tid];

    if (split == 0)
        out[(size_t)b * D_DIM + tid] = xv + acc;      // x + partial0 (x from register)
    else
        g_scratch[(size_t)b * D_DIM + tid] = acc;     // partial1
}

// combine: out += scratch, 8 independent float4 loads per thread (MLP=8)
#define CMB_THREADS 256
#define CMB_GRID 512
#define CMB_STRIDE ((size_t)CMB_GRID * CMB_THREADS)   // 131072 float4s per pass

__global__ void __launch_bounds__(CMB_THREADS)
combine_kernel(float* __restrict__ out) {
    size_t i = (size_t)blockIdx.x * CMB_THREADS + threadIdx.x;
    float4* o = (float4*)out;
    const float4* s = (const float4*)g_scratch;
    float4 a[4], c[4];
#pragma unroll
    for (int r = 0; r < 4; r++) {
        a[r] = o[i + r * CMB_STRIDE];
        c[r] = s[i + r * CMB_STRIDE];
    }
#pragma unroll
    for (int r = 0; r < 4; r++) {
        a[r].x += c[r].x; a[r].y += c[r].y; a[r].z += c[r].z; a[r].w += c[r].w;
        o[i + r * CMB_STRIDE] = a[r];
    }
}

extern "C" void kernel_launch(void* const* d_in, const int* in_sizes, int n_in,
                              void* d_out, int out_size) {
    const float* x       = (const float*)d_in[0];
    const int*   indices = (const int*)d_in[1];
    const float* weights = (const float*)d_in[2];
    const float* pool    = (const float*)d_in[3];
    float*       out     = (float*)d_out;

    cudaFuncSetAttribute(sparse_gather_kernel,
                         cudaFuncAttributeMaxDynamicSharedMemorySize, SMEM_BYTES);

    sparse_gather_kernel<<<B_DIM * SPLIT, THREADS, SMEM_BYTES>>>(
        x, indices, weights, pool, out);

    combine_kernel<<<CMB_GRID, CMB_THREADS>>>(out);
}